// round 7
// baseline (speedup 1.0000x reference)
#include <cuda_runtime.h>
#include <cuda_fp16.h>
#include <cstdint>

#define TOKENS 4096
#define DIN    4096
#define DOUT   4096
#define BM 128
#define BN 256
#define BK 64
#define NKT (DIN / BK)                 // 64 k-tiles
#define STG_BYTES ((BM + BN) * BK * 2) // 49152 B per stage
#define NSTAGE 4
#define SMEM_TOTAL (NSTAGE * STG_BYTES)  // 196608

// fp16 scratch (plain row-major, K contiguous)
__device__ __align__(128) __half g_A[(size_t)TOKENS * DIN];
__device__ __align__(128) __half g_B[(size_t)DOUT * DIN];

__device__ __forceinline__ uint32_t smem_u32(const void* p) {
    uint32_t a;
    asm("{ .reg .u64 t; cvta.to.shared.u64 t, %1; cvt.u32.u64 %0, t; }" : "=r"(a) : "l"(p));
    return a;
}
__device__ __forceinline__ void cpasync16(uint32_t s, const void* g) {
    asm volatile("cp.async.cg.shared.global [%0], [%1], 16;" :: "r"(s), "l"(g));
}
#define LDSM4(R, ADDR) \
    asm volatile("ldmatrix.sync.aligned.m8n8.x4.shared.b16 {%0,%1,%2,%3}, [%4];" \
                 : "=r"((R)[0]), "=r"((R)[1]), "=r"((R)[2]), "=r"((R)[3]) : "r"(ADDR))
__device__ __forceinline__ void mma16816(float c[4], const uint32_t a[4],
                                         uint32_t b0, uint32_t b1) {
    asm volatile(
        "mma.sync.aligned.m16n8k16.row.col.f32.f16.f16.f32 "
        "{%0,%1,%2,%3},{%4,%5,%6,%7},{%8,%9},{%0,%1,%2,%3};"
        : "+f"(c[0]), "+f"(c[1]), "+f"(c[2]), "+f"(c[3])
        : "r"(a[0]), "r"(a[1]), "r"(a[2]), "r"(a[3]), "r"(b0), "r"(b1));
}

// ---------------------------------------------------------------------------
// Kernel 1: x -> smooth*sign -> FWHT128 -> NVFP4 fake-quant -> fp16 row-major
// ---------------------------------------------------------------------------
__global__ void __launch_bounds__(256) k_prep_x(const float* __restrict__ x,
                                                const float* __restrict__ smooth,
                                                const float* __restrict__ sgn) {
    const int t = blockIdx.x;
    const int wid = threadIdx.x >> 5, lane = threadIdx.x & 31;
    const float* xr = x + (size_t)t * DIN;
    __half* orow = g_A + (size_t)t * DIN;
    const float inv = 0.08838834764831845f;  // 1/sqrt(128)

    for (int i = 0; i < 4; ++i) {
        const int base = (wid * 4 + i) * 128;
        float v[4];
        #pragma unroll
        for (int a = 0; a < 4; ++a) {
            int d = base + a * 32 + lane;
            v[a] = xr[d] * (smooth[d] * sgn[d]);
        }
        #pragma unroll
        for (int a = 0; a < 4; ++a) {
            #pragma unroll
            for (int h = 16; h >= 1; h >>= 1) {
                float o = __shfl_xor_sync(0xffffffffu, v[a], h);
                v[a] = (lane & h) ? (o - v[a]) : (v[a] + o);
            }
        }
        {
            float u0 = v[0] + v[1], u1 = v[0] - v[1];
            float u2 = v[2] + v[3], u3 = v[2] - v[3];
            v[0] = u0 + u2; v[2] = u0 - u2; v[1] = u1 + u3; v[3] = u1 - u3;
        }
        #pragma unroll
        for (int a = 0; a < 4; ++a) {
            float s = v[a] * inv;
            float m = fabsf(s);
            #pragma unroll
            for (int h = 1; h < 16; h <<= 1)
                m = fmaxf(m, __shfl_xor_sync(0xffffffffu, m, h));
            float amax  = fmaxf(m, 1e-12f);
            float scale = __fdiv_rn(amax, 6.0f);
            float an    = __fdiv_rn(fabsf(s), scale);
            float lvl = an <= 0.25f ? 0.0f : an <= 0.75f ? 0.5f :
                        an <= 1.25f ? 1.0f : an <= 1.75f ? 1.5f :
                        an <= 2.50f ? 2.0f : an <= 3.50f ? 3.0f :
                        an <= 5.00f ? 4.0f : 6.0f;
            float xq = __fmul_rn(copysignf(lvl, s), scale);
            orow[base + a * 32 + lane] = __float2half_rn(xq);
        }
    }
}

// ---------------------------------------------------------------------------
// Kernel 2: w [Dout,Din] fp32 -> fp16 row-major (8 elems/thread, coalesced)
// ---------------------------------------------------------------------------
__global__ void __launch_bounds__(256) k_prep_w(const float* __restrict__ w) {
    size_t idx = (size_t)blockIdx.x * 256u + threadIdx.x;
    size_t off = idx * 8u;
    const float4* p = (const float4*)(w + off);
    float4 f0 = p[0], f1 = p[1];
    __half2 h[4];
    h[0] = __floats2half2_rn(f0.x, f0.y); h[1] = __floats2half2_rn(f0.z, f0.w);
    h[2] = __floats2half2_rn(f1.x, f1.y); h[3] = __floats2half2_rn(f1.z, f1.w);
    *(uint4*)(g_B + off) = *(const uint4*)h;
}

// ---------------------------------------------------------------------------
// Kernel 3: GEMM 128x256x64, 4-stage cp.async, ldmatrix + mma.sync m16n8k16.
// 8 warps: 2(m) x 4(n); warp tile 64x64. SMEM 16B-chunk XOR swizzle.
// ---------------------------------------------------------------------------
__global__ void __launch_bounds__(256) k_gemm(const float* __restrict__ bias,
                                              float* __restrict__ out) {
    extern __shared__ __align__(128) unsigned char smem[];
    const uint32_t sb = smem_u32(smem);
    const int tid = threadIdx.x, lane = tid & 31, wid = tid >> 5;
    const int warp_m = wid & 1, warp_n = wid >> 1;
    const int tile_m = blockIdx.y * BM, tile_n = blockIdx.x * BN;

    auto load_stage = [&](int kt, int slot) {
        uint32_t base = sb + slot * STG_BYTES;
        const __half* gA = g_A + (size_t)tile_m * DIN + kt * BK;
        const __half* gB = g_B + (size_t)tile_n * DIN + kt * BK;
        #pragma unroll
        for (int i = 0; i < 4; ++i) {           // A: 128 rows x 8 chunks
            int c = tid + i * 256;
            int row = c >> 3, ch = c & 7;
            uint32_t sw = (uint32_t)((ch ^ (row & 7)) << 4);
            cpasync16(base + row * 128 + sw, gA + (size_t)row * DIN + ch * 8);
        }
        #pragma unroll
        for (int i = 0; i < 8; ++i) {           // B: 256 rows x 8 chunks
            int c = tid + i * 256;
            int row = c >> 3, ch = c & 7;
            uint32_t sw = (uint32_t)((ch ^ (row & 7)) << 4);
            cpasync16(base + 16384 + row * 128 + sw, gB + (size_t)row * DIN + ch * 8);
        }
        asm volatile("cp.async.commit_group;" ::: "memory");
    };

    float acc[4][8][4];
    #pragma unroll
    for (int f = 0; f < 4; ++f)
        #pragma unroll
        for (int n = 0; n < 8; ++n)
            #pragma unroll
            for (int j = 0; j < 4; ++j) acc[f][n][j] = 0.0f;

    load_stage(0, 0);
    load_stage(1, 1);
    load_stage(2, 2);

    // A x4 quads: (m+0,k0)(m+8,k0)(m+0,k8)(m+8,k8)
    const int a_row  = warp_m * 64 + (lane & 7) + ((lane >> 3) & 1) * 8;
    const int a_chad = lane >> 4;
    // B x4 quads: (n+0,k0)(n+0,k8)(n+8,k0)(n+8,k8)
    const int b_row  = warp_n * 64 + (lane & 7) + (lane >> 4) * 8;
    const int b_chad = (lane >> 3) & 1;

    for (int kt = 0; kt < NKT; ++kt) {
        const int slot = kt % NSTAGE;
        asm volatile("cp.async.wait_group 2;" ::: "memory");
        __syncthreads();
        if (kt + 3 < NKT) load_stage(kt + 3, (kt + 3) % NSTAGE);
        else asm volatile("cp.async.commit_group;" ::: "memory");

        const uint32_t aA = sb + slot * STG_BYTES;
        const uint32_t aB = aA + 16384;
        #pragma unroll
        for (int kk = 0; kk < 4; ++kk) {
            uint32_t af[4][4], bf[4][4];
            #pragma unroll
            for (int f = 0; f < 4; ++f) {
                int row = a_row + f * 16;
                int ch = kk * 2 + a_chad;
                LDSM4(af[f], aA + row * 128 + ((ch ^ (row & 7)) << 4));
            }
            #pragma unroll
            for (int g = 0; g < 4; ++g) {
                int row = b_row + g * 16;
                int ch = kk * 2 + b_chad;
                LDSM4(bf[g], aB + row * 128 + ((ch ^ (row & 7)) << 4));
            }
            #pragma unroll
            for (int f = 0; f < 4; ++f)
                #pragma unroll
                for (int g = 0; g < 4; ++g) {
                    mma16816(acc[f][g * 2 + 0], af[f], bf[g][0], bf[g][1]);
                    mma16816(acc[f][g * 2 + 1], af[f], bf[g][2], bf[g][3]);
                }
        }
    }

    // Epilogue: c0,c1 -> row, c2,c3 -> row+8; cols (lane&3)*2, +1
    #pragma unroll
    for (int n8 = 0; n8 < 8; ++n8) {
        int col = tile_n + warp_n * 64 + n8 * 8 + (lane & 3) * 2;
        float b0 = __ldg(bias + col), b1 = __ldg(bias + col + 1);
        #pragma unroll
        for (int f = 0; f < 4; ++f) {
            int row = tile_m + warp_m * 64 + f * 16 + (lane >> 2);
            float2 v0 = {acc[f][n8][0] + b0, acc[f][n8][1] + b1};
            float2 v1 = {acc[f][n8][2] + b0, acc[f][n8][3] + b1};
            *(float2*)(out + (size_t)row * DOUT + col) = v0;
            *(float2*)(out + (size_t)(row + 8) * DOUT + col) = v1;
        }
    }
}

extern "C" void kernel_launch(void* const* d_in, const int* in_sizes, int n_in,
                              void* d_out, int out_size) {
    const float* x      = (const float*)d_in[0];
    const float* smooth = (const float*)d_in[1];
    const float* sgn    = (const float*)d_in[2];
    // d_in[3] = H_block (Sylvester/sqrt(128); realized via FWHT, unused)
    const float* w      = (const float*)d_in[4];
    const float* bias   = (const float*)d_in[5];
    float* out = (float*)d_out;

    cudaFuncSetAttribute(k_gemm, cudaFuncAttributeMaxDynamicSharedMemorySize, SMEM_TOTAL);

    k_prep_x<<<TOKENS, 256>>>(x, smooth, sgn);
    k_prep_w<<<(DOUT * (DIN / 8)) / 256, 256>>>(w);
    k_gemm<<<dim3(DOUT / BN, TOKENS / BM), 256, SMEM_TOTAL>>>(bias, out);
}

// round 8
// speedup vs baseline: 1.1676x; 1.1676x over previous
#include <cuda_runtime.h>
#include <cuda_fp16.h>
#include <cstdint>

#define TOKENS 4096
#define DIN    4096
#define DOUT   4096
#define BM 128
#define BN 128
#define BK 64
#define NKT (DIN / BK)                 // 64 k-tiles
#define STG_BYTES ((BM + BN) * BK * 2) // 32768 B per stage
#define NSTAGE 3
#define SMEM_TOTAL (NSTAGE * STG_BYTES)  // 98304 -> 2 CTAs/SM

// fp16 scratch (plain row-major, K contiguous)
__device__ __align__(128) __half g_A[(size_t)TOKENS * DIN];
__device__ __align__(128) __half g_B[(size_t)DOUT * DIN];

__device__ __forceinline__ uint32_t smem_u32(const void* p) {
    uint32_t a;
    asm("{ .reg .u64 t; cvta.to.shared.u64 t, %1; cvt.u32.u64 %0, t; }" : "=r"(a) : "l"(p));
    return a;
}
__device__ __forceinline__ void cpasync16(uint32_t s, const void* g) {
    asm volatile("cp.async.cg.shared.global [%0], [%1], 16;" :: "r"(s), "l"(g));
}
#define LDSM4(R, ADDR) \
    asm volatile("ldmatrix.sync.aligned.m8n8.x4.shared.b16 {%0,%1,%2,%3}, [%4];" \
                 : "=r"((R)[0]), "=r"((R)[1]), "=r"((R)[2]), "=r"((R)[3]) : "r"(ADDR))
__device__ __forceinline__ void mma16816(float c[4], const uint32_t a[4],
                                         uint32_t b0, uint32_t b1) {
    asm volatile(
        "mma.sync.aligned.m16n8k16.row.col.f32.f16.f16.f32 "
        "{%0,%1,%2,%3},{%4,%5,%6,%7},{%8,%9},{%0,%1,%2,%3};"
        : "+f"(c[0]), "+f"(c[1]), "+f"(c[2]), "+f"(c[3])
        : "r"(a[0]), "r"(a[1]), "r"(a[2]), "r"(a[3]), "r"(b0), "r"(b1));
}

// ---------------------------------------------------------------------------
// Fused prep: CTAs [0,4096) do x -> smooth*sign -> FWHT128 -> NVFP4 -> fp16;
// CTAs [4096,12288) convert w fp32 -> fp16 (8 elems/thread, coalesced).
// Independent work; one launch lets BW-bound w-part overlap issue-bound x-part.
// ---------------------------------------------------------------------------
__global__ void __launch_bounds__(256) k_prep(const float* __restrict__ x,
                                              const float* __restrict__ smooth,
                                              const float* __restrict__ sgn,
                                              const float* __restrict__ w) {
    if (blockIdx.x >= TOKENS) {
        size_t idx = (size_t)(blockIdx.x - TOKENS) * 256u + threadIdx.x;
        size_t off = idx * 8u;
        const float4* p = (const float4*)(w + off);
        float4 f0 = p[0], f1 = p[1];
        __half2 h[4];
        h[0] = __floats2half2_rn(f0.x, f0.y); h[1] = __floats2half2_rn(f0.z, f0.w);
        h[2] = __floats2half2_rn(f1.x, f1.y); h[3] = __floats2half2_rn(f1.z, f1.w);
        *(uint4*)(g_B + off) = *(const uint4*)h;
        return;
    }
    const int t = blockIdx.x;
    const int wid = threadIdx.x >> 5, lane = threadIdx.x & 31;
    const float* xr = x + (size_t)t * DIN;
    __half* orow = g_A + (size_t)t * DIN;
    const float inv = 0.08838834764831845f;  // 1/sqrt(128)

    for (int i = 0; i < 4; ++i) {
        const int base = (wid * 4 + i) * 128;
        float v[4];
        #pragma unroll
        for (int a = 0; a < 4; ++a) {
            int d = base + a * 32 + lane;
            v[a] = xr[d] * (smooth[d] * sgn[d]);
        }
        #pragma unroll
        for (int a = 0; a < 4; ++a) {
            #pragma unroll
            for (int h = 16; h >= 1; h >>= 1) {
                float o = __shfl_xor_sync(0xffffffffu, v[a], h);
                v[a] = (lane & h) ? (o - v[a]) : (v[a] + o);
            }
        }
        {
            float u0 = v[0] + v[1], u1 = v[0] - v[1];
            float u2 = v[2] + v[3], u3 = v[2] - v[3];
            v[0] = u0 + u2; v[2] = u0 - u2; v[1] = u1 + u3; v[3] = u1 - u3;
        }
        #pragma unroll
        for (int a = 0; a < 4; ++a) {
            float s = v[a] * inv;
            float m = fabsf(s);
            #pragma unroll
            for (int h = 1; h < 16; h <<= 1)
                m = fmaxf(m, __shfl_xor_sync(0xffffffffu, m, h));
            float amax  = fmaxf(m, 1e-12f);
            float scale = __fdiv_rn(amax, 6.0f);
            float an    = __fdiv_rn(fabsf(s), scale);
            float lvl = an <= 0.25f ? 0.0f : an <= 0.75f ? 0.5f :
                        an <= 1.25f ? 1.0f : an <= 1.75f ? 1.5f :
                        an <= 2.50f ? 2.0f : an <= 3.50f ? 3.0f :
                        an <= 5.00f ? 4.0f : 6.0f;
            float xq = __fmul_rn(copysignf(lvl, s), scale);
            orow[base + a * 32 + lane] = __float2half_rn(xq);
        }
    }
}

// ---------------------------------------------------------------------------
// GEMM 128x128x64, 3-stage cp.async, ldmatrix + mma.sync m16n8k16.
// Warp layout: 2(m) x 4(n); warp tile 64x32. 2 CTAs/SM (R3 measured config).
// ---------------------------------------------------------------------------
__global__ void __launch_bounds__(256, 2) k_gemm(const float* __restrict__ bias,
                                                 float* __restrict__ out) {
    extern __shared__ __align__(128) unsigned char smem[];
    const uint32_t sb = smem_u32(smem);
    const int tid = threadIdx.x, lane = tid & 31, wid = tid >> 5;
    const int warp_m = wid & 1, warp_n = wid >> 1;
    const int tile_m = blockIdx.y * BM, tile_n = blockIdx.x * BN;

    auto load_stage = [&](int kt, int slot) {
        uint32_t base = sb + slot * STG_BYTES;
        const __half* gA = g_A + (size_t)tile_m * DIN + kt * BK;
        const __half* gB = g_B + (size_t)tile_n * DIN + kt * BK;
        #pragma unroll
        for (int i = 0; i < 4; ++i) {
            int c = tid + i * 256;
            int row = c >> 3, ch = c & 7;
            uint32_t sw = (uint32_t)((ch ^ (row & 7)) << 4);
            cpasync16(base + row * 128 + sw, gA + (size_t)row * DIN + ch * 8);
            cpasync16(base + 16384 + row * 128 + sw, gB + (size_t)row * DIN + ch * 8);
        }
        asm volatile("cp.async.commit_group;" ::: "memory");
    };

    float acc[4][4][4];
    #pragma unroll
    for (int f = 0; f < 4; ++f)
        #pragma unroll
        for (int n = 0; n < 4; ++n)
            #pragma unroll
            for (int j = 0; j < 4; ++j) acc[f][n][j] = 0.0f;

    load_stage(0, 0);
    load_stage(1, 1);

    // A x4 quads: (m+0,k0)(m+8,k0)(m+0,k8)(m+8,k8)
    const int a_row  = warp_m * 64 + (lane & 7) + ((lane >> 3) & 1) * 8;
    const int a_chad = lane >> 4;
    // B x4 quads: (n+0,k0)(n+0,k8)(n+8,k0)(n+8,k8)
    const int b_row  = warp_n * 32 + (lane & 7) + (lane >> 4) * 8;
    const int b_chad = (lane >> 3) & 1;

    for (int kt = 0; kt < NKT; ++kt) {
        const int slot = kt % NSTAGE;
        if (kt == NKT - 1) asm volatile("cp.async.wait_group 0;" ::: "memory");
        else               asm volatile("cp.async.wait_group 1;" ::: "memory");
        __syncthreads();
        if (kt + 2 < NKT) load_stage(kt + 2, (kt + 2) % NSTAGE);

        const uint32_t aA = sb + slot * STG_BYTES;
        const uint32_t aB = aA + 16384;
        #pragma unroll
        for (int kk = 0; kk < 4; ++kk) {
            uint32_t af[4][4], bf[2][4];
            #pragma unroll
            for (int f = 0; f < 4; ++f) {
                int row = a_row + f * 16;
                int ch = kk * 2 + a_chad;
                LDSM4(af[f], aA + row * 128 + ((ch ^ (row & 7)) << 4));
            }
            #pragma unroll
            for (int g = 0; g < 2; ++g) {
                int row = b_row + g * 16;
                int ch = kk * 2 + b_chad;
                LDSM4(bf[g], aB + row * 128 + ((ch ^ (row & 7)) << 4));
            }
            #pragma unroll
            for (int f = 0; f < 4; ++f) {
                mma16816(acc[f][0], af[f], bf[0][0], bf[0][1]);
                mma16816(acc[f][1], af[f], bf[0][2], bf[0][3]);
                mma16816(acc[f][2], af[f], bf[1][0], bf[1][1]);
                mma16816(acc[f][3], af[f], bf[1][2], bf[1][3]);
            }
        }
    }

    #pragma unroll
    for (int n8 = 0; n8 < 4; ++n8) {
        int col = tile_n + warp_n * 32 + n8 * 8 + (lane & 3) * 2;
        float b0 = __ldg(bias + col), b1 = __ldg(bias + col + 1);
        #pragma unroll
        for (int f = 0; f < 4; ++f) {
            int row = tile_m + warp_m * 64 + f * 16 + (lane >> 2);
            float2 v0 = {acc[f][n8][0] + b0, acc[f][n8][1] + b1};
            float2 v1 = {acc[f][n8][2] + b0, acc[f][n8][3] + b1};
            *(float2*)(out + (size_t)row * DOUT + col) = v0;
            *(float2*)(out + (size_t)(row + 8) * DOUT + col) = v1;
        }
    }
}

extern "C" void kernel_launch(void* const* d_in, const int* in_sizes, int n_in,
                              void* d_out, int out_size) {
    const float* x      = (const float*)d_in[0];
    const float* smooth = (const float*)d_in[1];
    const float* sgn    = (const float*)d_in[2];
    // d_in[3] = H_block (Sylvester/sqrt(128); realized via FWHT, unused)
    const float* w      = (const float*)d_in[4];
    const float* bias   = (const float*)d_in[5];
    float* out = (float*)d_out;

    cudaFuncSetAttribute(k_gemm, cudaFuncAttributeMaxDynamicSharedMemorySize, SMEM_TOTAL);

    // 4096 x-CTAs + 8192 w-CTAs in one launch (independent work, overlapped)
    k_prep<<<TOKENS + (DOUT * (DIN / 8)) / 256, 256>>>(x, smooth, sgn, w);
    k_gemm<<<dim3(DOUT / BN, TOKENS / BM), 256, SMEM_TOTAL>>>(bias, out);
}

// round 10
// speedup vs baseline: 1.1967x; 1.0250x over previous
#include <cuda_runtime.h>
#include <cuda_fp16.h>
#include <cstdint>

#define TOKENS 4096
#define DIN    4096
#define DOUT   4096
#define BM 128
#define BN 128
#define BK 64
#define NKT (DIN / BK)                 // 64 k-tiles
#define STG_BYTES ((BM + BN) * BK * 2) // 32768 B per stage
#define NSTAGE 3
#define SMEM_TOTAL (NSTAGE * STG_BYTES)  // 98304 -> 2 CTAs/SM

// fp16 scratch (plain row-major, K contiguous)
__device__ __align__(128) __half g_A[(size_t)TOKENS * DIN];
__device__ __align__(128) __half g_B[(size_t)DOUT * DIN];

__device__ __forceinline__ uint32_t smem_u32(const void* p) {
    uint32_t a;
    asm("{ .reg .u64 t; cvta.to.shared.u64 t, %1; cvt.u32.u64 %0, t; }" : "=r"(a) : "l"(p));
    return a;
}
__device__ __forceinline__ void cpasync16(uint32_t s, const void* g) {
    asm volatile("cp.async.cg.shared.global [%0], [%1], 16;" :: "r"(s), "l"(g));
}
#define LDSM4(R, ADDR) \
    asm volatile("ldmatrix.sync.aligned.m8n8.x4.shared.b16 {%0,%1,%2,%3}, [%4];" \
                 : "=r"((R)[0]), "=r"((R)[1]), "=r"((R)[2]), "=r"((R)[3]) : "r"(ADDR))
__device__ __forceinline__ void mma16816(float c[4], const uint32_t a[4],
                                         uint32_t b0, uint32_t b1) {
    asm volatile(
        "mma.sync.aligned.m16n8k16.row.col.f32.f16.f16.f32 "
        "{%0,%1,%2,%3},{%4,%5,%6,%7},{%8,%9},{%0,%1,%2,%3};"
        : "+f"(c[0]), "+f"(c[1]), "+f"(c[2]), "+f"(c[3])
        : "r"(a[0]), "r"(a[1]), "r"(a[2]), "r"(a[3]), "r"(b0), "r"(b1));
}

// ---------------------------------------------------------------------------
// Fused prep: CTAs [0,4096) do x -> smooth*sign -> FWHT128 -> NVFP4 -> fp16;
// CTAs [4096,12288) convert w fp32 -> fp16 (8 elems/thread, coalesced).
// ---------------------------------------------------------------------------
__global__ void __launch_bounds__(256) k_prep(const float* __restrict__ x,
                                              const float* __restrict__ smooth,
                                              const float* __restrict__ sgn,
                                              const float* __restrict__ w) {
    if (blockIdx.x >= TOKENS) {
        size_t idx = (size_t)(blockIdx.x - TOKENS) * 256u + threadIdx.x;
        size_t off = idx * 8u;
        const float4* p = (const float4*)(w + off);
        float4 f0 = p[0], f1 = p[1];
        __half2 h[4];
        h[0] = __floats2half2_rn(f0.x, f0.y); h[1] = __floats2half2_rn(f0.z, f0.w);
        h[2] = __floats2half2_rn(f1.x, f1.y); h[3] = __floats2half2_rn(f1.z, f1.w);
        *(uint4*)(g_B + off) = *(const uint4*)h;
        return;
    }
    const int t = blockIdx.x;
    const int wid = threadIdx.x >> 5, lane = threadIdx.x & 31;
    const float* xr = x + (size_t)t * DIN;
    __half* orow = g_A + (size_t)t * DIN;
    const float inv = 0.08838834764831845f;  // 1/sqrt(128)

    for (int i = 0; i < 4; ++i) {
        const int base = (wid * 4 + i) * 128;
        float v[4];
        #pragma unroll
        for (int a = 0; a < 4; ++a) {
            int d = base + a * 32 + lane;
            v[a] = xr[d] * (smooth[d] * sgn[d]);
        }
        #pragma unroll
        for (int a = 0; a < 4; ++a) {
            #pragma unroll
            for (int h = 16; h >= 1; h >>= 1) {
                float o = __shfl_xor_sync(0xffffffffu, v[a], h);
                v[a] = (lane & h) ? (o - v[a]) : (v[a] + o);
            }
        }
        {
            float u0 = v[0] + v[1], u1 = v[0] - v[1];
            float u2 = v[2] + v[3], u3 = v[2] - v[3];
            v[0] = u0 + u2; v[2] = u0 - u2; v[1] = u1 + u3; v[3] = u1 - u3;
        }
        #pragma unroll
        for (int a = 0; a < 4; ++a) {
            float s = v[a] * inv;
            float m = fabsf(s);
            #pragma unroll
            for (int h = 1; h < 16; h <<= 1)
                m = fmaxf(m, __shfl_xor_sync(0xffffffffu, m, h));
            float amax  = fmaxf(m, 1e-12f);
            float scale = __fdiv_rn(amax, 6.0f);
            float an    = __fdiv_rn(fabsf(s), scale);
            float lvl = an <= 0.25f ? 0.0f : an <= 0.75f ? 0.5f :
                        an <= 1.25f ? 1.0f : an <= 1.75f ? 1.5f :
                        an <= 2.50f ? 2.0f : an <= 3.50f ? 3.0f :
                        an <= 5.00f ? 4.0f : 6.0f;
            float xq = __fmul_rn(copysignf(lvl, s), scale);
            orow[base + a * 32 + lane] = __float2half_rn(xq);
        }
    }
}

// ---------------------------------------------------------------------------
// GEMM 128x128x64: 4 warps (2m x 2n), warp tile 64x64, double-buffered
// fragments, 3-stage cp.async, 2 CTAs/SM (256 regs/thread available).
// ---------------------------------------------------------------------------
__global__ void __launch_bounds__(128, 2) k_gemm(const float* __restrict__ bias,
                                                 float* __restrict__ out) {
    extern __shared__ __align__(128) unsigned char smem[];
    const uint32_t sb = smem_u32(smem);
    const int tid = threadIdx.x, lane = tid & 31, wid = tid >> 5;
    const int warp_m = wid & 1, warp_n = wid >> 1;
    const int tile_m = blockIdx.y * BM, tile_n = blockIdx.x * BN;

    auto load_stage = [&](int kt, int slot) {
        uint32_t base = sb + slot * STG_BYTES;
        const __half* gA = g_A + (size_t)tile_m * DIN + kt * BK;
        const __half* gB = g_B + (size_t)tile_n * DIN + kt * BK;
        #pragma unroll
        for (int i = 0; i < 8; ++i) {           // A: 128 rows x 8 chunks
            int c = tid + i * 128;
            int row = c >> 3, ch = c & 7;
            uint32_t sw = (uint32_t)((ch ^ (row & 7)) << 4);
            cpasync16(base + row * 128 + sw, gA + (size_t)row * DIN + ch * 8);
        }
        #pragma unroll
        for (int i = 0; i < 8; ++i) {           // B: 128 rows x 8 chunks
            int c = tid + i * 128;
            int row = c >> 3, ch = c & 7;
            uint32_t sw = (uint32_t)((ch ^ (row & 7)) << 4);
            cpasync16(base + 16384 + row * 128 + sw, gB + (size_t)row * DIN + ch * 8);
        }
        asm volatile("cp.async.commit_group;" ::: "memory");
    };

    float acc[4][8][4];
    #pragma unroll
    for (int f = 0; f < 4; ++f)
        #pragma unroll
        for (int n = 0; n < 8; ++n)
            #pragma unroll
            for (int j = 0; j < 4; ++j) acc[f][n][j] = 0.0f;

    load_stage(0, 0);
    load_stage(1, 1);

    // A x4 quads: (m+0,k0)(m+8,k0)(m+0,k8)(m+8,k8)
    const int a_row  = warp_m * 64 + (lane & 7) + ((lane >> 3) & 1) * 8;
    const int a_chad = lane >> 4;
    // B x4 quads: (n+0,k0)(n+0,k8)(n+8,k0)(n+8,k8)
    const int b_row  = warp_n * 64 + (lane & 7) + (lane >> 4) * 8;
    const int b_chad = (lane >> 3) & 1;

    uint32_t af[2][4][4], bf[2][4][4];

    auto load_frags = [&](int kk, int buf, uint32_t aA, uint32_t aB) {
        #pragma unroll
        for (int f = 0; f < 4; ++f) {
            int row = a_row + f * 16;
            int ch = kk * 2 + a_chad;
            LDSM4(af[buf][f], aA + row * 128 + ((ch ^ (row & 7)) << 4));
        }
        #pragma unroll
        for (int g = 0; g < 4; ++g) {
            int row = b_row + g * 16;
            int ch = kk * 2 + b_chad;
            LDSM4(bf[buf][g], aB + row * 128 + ((ch ^ (row & 7)) << 4));
        }
    };

    for (int kt = 0; kt < NKT; ++kt) {
        const int slot = kt % NSTAGE;
        if (kt == NKT - 1) asm volatile("cp.async.wait_group 0;" ::: "memory");
        else               asm volatile("cp.async.wait_group 1;" ::: "memory");
        __syncthreads();
        if (kt + 2 < NKT) load_stage(kt + 2, (kt + 2) % NSTAGE);

        const uint32_t aA = sb + slot * STG_BYTES;
        const uint32_t aB = aA + 16384;
        load_frags(0, 0, aA, aB);
        #pragma unroll
        for (int kk = 0; kk < 4; ++kk) {
            const int cur = kk & 1;
            if (kk < 3) load_frags(kk + 1, cur ^ 1, aA, aB);
            #pragma unroll
            for (int f = 0; f < 4; ++f)
                #pragma unroll
                for (int g = 0; g < 4; ++g) {
                    mma16816(acc[f][g * 2 + 0], af[cur][f], bf[cur][g][0], bf[cur][g][1]);
                    mma16816(acc[f][g * 2 + 1], af[cur][f], bf[cur][g][2], bf[cur][g][3]);
                }
        }
    }

    // Epilogue: c0,c1 -> row, c2,c3 -> row+8; cols (lane&3)*2, +1
    #pragma unroll
    for (int n8 = 0; n8 < 8; ++n8) {
        int col = tile_n + warp_n * 64 + n8 * 8 + (lane & 3) * 2;
        float b0 = __ldg(bias + col), b1 = __ldg(bias + col + 1);
        #pragma unroll
        for (int f = 0; f < 4; ++f) {
            int row = tile_m + warp_m * 64 + f * 16 + (lane >> 2);
            float2 v0 = {acc[f][n8][0] + b0, acc[f][n8][1] + b1};
            float2 v1 = {acc[f][n8][2] + b0, acc[f][n8][3] + b1};
            *(float2*)(out + (size_t)row * DOUT + col) = v0;
            *(float2*)(out + (size_t)(row + 8) * DOUT + col) = v1;
        }
    }
}

extern "C" void kernel_launch(void* const* d_in, const int* in_sizes, int n_in,
                              void* d_out, int out_size) {
    const float* x      = (const float*)d_in[0];
    const float* smooth = (const float*)d_in[1];
    const float* sgn    = (const float*)d_in[2];
    // d_in[3] = H_block (Sylvester/sqrt(128); realized via FWHT, unused)
    const float* w      = (const float*)d_in[4];
    const float* bias   = (const float*)d_in[5];
    float* out = (float*)d_out;

    cudaFuncSetAttribute(k_gemm, cudaFuncAttributeMaxDynamicSharedMemorySize, SMEM_TOTAL);

    k_prep<<<TOKENS + (DOUT * (DIN / 8)) / 256, 256>>>(x, smooth, sgn, w);
    k_gemm<<<dim3(DOUT / BN, TOKENS / BM), 128, SMEM_TOTAL>>>(bias, out);
}

// round 12
// speedup vs baseline: 1.3902x; 1.1617x over previous
#include <cuda_runtime.h>
#include <cuda_fp16.h>
#include <cstdint>

#define TOKENS 4096
#define DIN    4096
#define DOUT   4096
#define BM 128
#define BN 128
#define BK 64
#define NKT (DIN / BK)                 // 64 k-tiles
#define STG_BYTES ((BM + BN) * BK * 2) // 32768 B per stage
#define NSTAGE 3
#define SMEM_TOTAL (NSTAGE * STG_BYTES)  // 98304 -> 2 CTAs/SM

// fp16 scratch (plain row-major, K contiguous)
__device__ __align__(128) __half g_A[(size_t)TOKENS * DIN];
__device__ __align__(128) __half g_B[(size_t)DOUT * DIN];

__device__ __forceinline__ uint32_t smem_u32(const void* p) {
    uint32_t a;
    asm("{ .reg .u64 t; cvta.to.shared.u64 t, %1; cvt.u32.u64 %0, t; }" : "=r"(a) : "l"(p));
    return a;
}
__device__ __forceinline__ void cpasync16(uint32_t s, const void* g) {
    asm volatile("cp.async.cg.shared.global [%0], [%1], 16;" :: "r"(s), "l"(g));
}
#define LDSM4(R, ADDR) \
    asm volatile("ldmatrix.sync.aligned.m8n8.x4.shared.b16 {%0,%1,%2,%3}, [%4];" \
                 : "=r"((R)[0]), "=r"((R)[1]), "=r"((R)[2]), "=r"((R)[3]) : "r"(ADDR))
__device__ __forceinline__ void mma16816(float c[4], const uint32_t a[4],
                                         uint32_t b0, uint32_t b1) {
    asm volatile(
        "mma.sync.aligned.m16n8k16.row.col.f32.f16.f16.f32 "
        "{%0,%1,%2,%3},{%4,%5,%6,%7},{%8,%9},{%0,%1,%2,%3};"
        : "+f"(c[0]), "+f"(c[1]), "+f"(c[2]), "+f"(c[3])
        : "r"(a[0]), "r"(a[1]), "r"(a[2]), "r"(a[3]), "r"(b0), "r"(b1));
}

// ---------------------------------------------------------------------------
// Fused prep: CTAs [0,4096) do x -> smooth*sign -> FWHT128 -> NVFP4 -> fp16;
// CTAs [4096,12288) convert w fp32 -> fp16 (8 elems/thread, coalesced).
// ---------------------------------------------------------------------------
__global__ void __launch_bounds__(256) k_prep(const float* __restrict__ x,
                                              const float* __restrict__ smooth,
                                              const float* __restrict__ sgn,
                                              const float* __restrict__ w) {
    if (blockIdx.x >= TOKENS) {
        size_t idx = (size_t)(blockIdx.x - TOKENS) * 256u + threadIdx.x;
        size_t off = idx * 8u;
        const float4* p = (const float4*)(w + off);
        float4 f0 = p[0], f1 = p[1];
        __half2 h[4];
        h[0] = __floats2half2_rn(f0.x, f0.y); h[1] = __floats2half2_rn(f0.z, f0.w);
        h[2] = __floats2half2_rn(f1.x, f1.y); h[3] = __floats2half2_rn(f1.z, f1.w);
        *(uint4*)(g_B + off) = *(const uint4*)h;
        return;
    }
    const int t = blockIdx.x;
    const int wid = threadIdx.x >> 5, lane = threadIdx.x & 31;
    const float* xr = x + (size_t)t * DIN;
    __half* orow = g_A + (size_t)t * DIN;
    const float inv = 0.08838834764831845f;  // 1/sqrt(128)

    for (int i = 0; i < 4; ++i) {
        const int base = (wid * 4 + i) * 128;
        float v[4];
        #pragma unroll
        for (int a = 0; a < 4; ++a) {
            int d = base + a * 32 + lane;
            v[a] = xr[d] * (smooth[d] * sgn[d]);
        }
        #pragma unroll
        for (int a = 0; a < 4; ++a) {
            #pragma unroll
            for (int h = 16; h >= 1; h >>= 1) {
                float o = __shfl_xor_sync(0xffffffffu, v[a], h);
                v[a] = (lane & h) ? (o - v[a]) : (v[a] + o);
            }
        }
        {
            float u0 = v[0] + v[1], u1 = v[0] - v[1];
            float u2 = v[2] + v[3], u3 = v[2] - v[3];
            v[0] = u0 + u2; v[2] = u0 - u2; v[1] = u1 + u3; v[3] = u1 - u3;
        }
        #pragma unroll
        for (int a = 0; a < 4; ++a) {
            float s = v[a] * inv;
            float m = fabsf(s);
            #pragma unroll
            for (int h = 1; h < 16; h <<= 1)
                m = fmaxf(m, __shfl_xor_sync(0xffffffffu, m, h));
            float amax  = fmaxf(m, 1e-12f);
            float scale = __fdiv_rn(amax, 6.0f);
            float an    = __fdiv_rn(fabsf(s), scale);
            float lvl = an <= 0.25f ? 0.0f : an <= 0.75f ? 0.5f :
                        an <= 1.25f ? 1.0f : an <= 1.75f ? 1.5f :
                        an <= 2.50f ? 2.0f : an <= 3.50f ? 3.0f :
                        an <= 5.00f ? 4.0f : 6.0f;
            float xq = __fmul_rn(copysignf(lvl, s), scale);
            orow[base + a * 32 + lane] = __float2half_rn(xq);
        }
    }
}

// ---------------------------------------------------------------------------
// GEMM 128x128x64: 4 warps (2m x 2n), warp tile 64x64, fragment double-buffer
// with CROSS-STAGE kk0 prefetch (barrier between kk2 and kk3), 3-stage
// cp.async pipeline with 2-iteration lookahead, 2 CTAs/SM.
// ---------------------------------------------------------------------------
__global__ void __launch_bounds__(128, 2) k_gemm(const float* __restrict__ bias,
                                                 float* __restrict__ out) {
    extern __shared__ __align__(128) unsigned char smem[];
    const uint32_t sb = smem_u32(smem);
    const int tid = threadIdx.x, lane = tid & 31, wid = tid >> 5;
    const int warp_m = wid & 1, warp_n = wid >> 1;
    const int tile_m = blockIdx.y * BM, tile_n = blockIdx.x * BN;

    auto load_stage = [&](int kt, int slot) {
        uint32_t base = sb + slot * STG_BYTES;
        const __half* gA = g_A + (size_t)tile_m * DIN + kt * BK;
        const __half* gB = g_B + (size_t)tile_n * DIN + kt * BK;
        #pragma unroll
        for (int i = 0; i < 8; ++i) {
            int c = tid + i * 128;
            int row = c >> 3, ch = c & 7;
            uint32_t sw = (uint32_t)((ch ^ (row & 7)) << 4);
            cpasync16(base + row * 128 + sw, gA + (size_t)row * DIN + ch * 8);
        }
        #pragma unroll
        for (int i = 0; i < 8; ++i) {
            int c = tid + i * 128;
            int row = c >> 3, ch = c & 7;
            uint32_t sw = (uint32_t)((ch ^ (row & 7)) << 4);
            cpasync16(base + 16384 + row * 128 + sw, gB + (size_t)row * DIN + ch * 8);
        }
        asm volatile("cp.async.commit_group;" ::: "memory");
    };

    float acc[4][8][4];
    #pragma unroll
    for (int f = 0; f < 4; ++f)
        #pragma unroll
        for (int n = 0; n < 8; ++n)
            #pragma unroll
            for (int j = 0; j < 4; ++j) acc[f][n][j] = 0.0f;

    // A x4 quads: (m+0,k0)(m+8,k0)(m+0,k8)(m+8,k8)
    const int a_row  = warp_m * 64 + (lane & 7) + ((lane >> 3) & 1) * 8;
    const int a_chad = lane >> 4;
    // B x4 quads: (n+0,k0)(n+0,k8)(n+8,k0)(n+8,k8)
    const int b_row  = warp_n * 64 + (lane & 7) + (lane >> 4) * 8;
    const int b_chad = (lane >> 3) & 1;

    uint32_t af[2][4][4], bf[2][4][4];

    auto load_frags = [&](int kk, int buf, uint32_t aA, uint32_t aB) {
        #pragma unroll
        for (int f = 0; f < 4; ++f) {
            int row = a_row + f * 16;
            int ch = kk * 2 + a_chad;
            LDSM4(af[buf][f], aA + row * 128 + ((ch ^ (row & 7)) << 4));
        }
        #pragma unroll
        for (int g = 0; g < 4; ++g) {
            int row = b_row + g * 16;
            int ch = kk * 2 + b_chad;
            LDSM4(bf[buf][g], aB + row * 128 + ((ch ^ (row & 7)) << 4));
        }
    };

    auto mma_chunk = [&](int buf) {
        #pragma unroll
        for (int f = 0; f < 4; ++f)
            #pragma unroll
            for (int g = 0; g < 4; ++g) {
                mma16816(acc[f][g * 2 + 0], af[buf][f], bf[buf][g][0], bf[buf][g][1]);
                mma16816(acc[f][g * 2 + 1], af[buf][f], bf[buf][g][2], bf[buf][g][3]);
            }
    };

    // Prologue: fill 3 stages; get stage 0 resident, preload its kk0 frags.
    load_stage(0, 0);
    load_stage(1, 1);
    load_stage(2, 2);
    asm volatile("cp.async.wait_group 2;" ::: "memory");
    __syncthreads();
    {
        uint32_t aA0 = sb;  // slot 0
        load_frags(0, 0, aA0, aA0 + 16384);
    }

    for (int kt = 0; kt < NKT; ++kt) {
        const uint32_t aA = sb + (kt % NSTAGE) * STG_BYTES;
        const uint32_t aB = aA + 16384;
        // kk = 0,1,2: load kk+1 frags (other buffer), then MMA current buffer
        #pragma unroll
        for (int kk = 0; kk < 3; ++kk) {
            load_frags(kk + 1, (kk + 1) & 1, aA, aB);
            mma_chunk(kk & 1);
        }
        // Publish stage kt+1 (committed 2 iterations ago) to all threads.
        asm volatile("cp.async.wait_group 1;" ::: "memory");
        __syncthreads();
        // Stage kt's smem is now dead (kk3 frags in regs) -> reuse its slot.
        if (kt + 3 < NKT) load_stage(kt + 3, kt % NSTAGE);
        // Cross-stage prefetch: kk0 of stage kt+1 into buf0.
        if (kt + 1 < NKT) {
            const uint32_t nA = sb + ((kt + 1) % NSTAGE) * STG_BYTES;
            load_frags(0, 0, nA, nA + 16384);
        }
        mma_chunk(1);   // kk=3
    }

    // Epilogue: c0,c1 -> row, c2,c3 -> row+8; cols (lane&3)*2, +1
    #pragma unroll
    for (int n8 = 0; n8 < 8; ++n8) {
        int col = tile_n + warp_n * 64 + n8 * 8 + (lane & 3) * 2;
        float b0 = __ldg(bias + col), b1 = __ldg(bias + col + 1);
        #pragma unroll
        for (int f = 0; f < 4; ++f) {
            int row = tile_m + warp_m * 64 + f * 16 + (lane >> 2);
            float2 v0 = {acc[f][n8][0] + b0, acc[f][n8][1] + b1};
            float2 v1 = {acc[f][n8][2] + b0, acc[f][n8][3] + b1};
            *(float2*)(out + (size_t)row * DOUT + col) = v0;
            *(float2*)(out + (size_t)(row + 8) * DOUT + col) = v1;
        }
    }
}

extern "C" void kernel_launch(void* const* d_in, const int* in_sizes, int n_in,
                              void* d_out, int out_size) {
    const float* x      = (const float*)d_in[0];
    const float* smooth = (const float*)d_in[1];
    const float* sgn    = (const float*)d_in[2];
    // d_in[3] = H_block (Sylvester/sqrt(128); realized via FWHT, unused)
    const float* w      = (const float*)d_in[4];
    const float* bias   = (const float*)d_in[5];
    float* out = (float*)d_out;

    cudaFuncSetAttribute(k_gemm, cudaFuncAttributeMaxDynamicSharedMemorySize, SMEM_TOTAL);

    k_prep<<<TOKENS + (DOUT * (DIN / 8)) / 256, 256>>>(x, smooth, sgn, w);
    k_gemm<<<dim3(DOUT / BN, TOKENS / BM), 128, SMEM_TOTAL>>>(bias, out);
}